// round 15
// baseline (speedup 1.0000x reference)
#include <cuda_runtime.h>
#include <cuda_bf16.h>
#include <cstdint>

#define HD 150
#define HP 160
#define GDIM 1000
#define GRIDW 129
#define NCHUNK 16
#define CHW 4864          // words per 152-row B chunk
#define CHB 19456         // bytes per 152-row B chunk (1024-aligned)

typedef unsigned long long ull;

// ---------------- helpers ----------------
__device__ __forceinline__ uint32_t smem_u32(const void* p){
    uint32_t a; asm("{ .reg .u64 t; cvta.to.shared.u64 t, %1; cvt.u32.u64 %0, t; }" : "=r"(a) : "l"(p));
    return a;
}
__device__ __forceinline__ uint32_t mul2(uint32_t a, uint32_t b){
    uint32_t r; asm("mul.bf16x2 %0,%1,%2;" : "=r"(r) : "r"(a), "r"(b)); return r;
}
#define CVTB2(res,a,b) asm("cvt.rn.satfinite.bf16x2.f32 %0, %1, %2;" : "=r"(res) : "f"(b), "f"(a))
#define STS128(r0,r1,r2,r3,addr) asm volatile("st.shared.v4.b32 [%0], {%1,%2,%3,%4};" :: "r"(addr), "r"(r0), "r"(r1), "r"(r2), "r"(r3) : "memory")
#define LDS128(r0,r1,r2,r3,addr) asm volatile("ld.shared.v4.b32 {%0,%1,%2,%3}, [%4];" : "=r"(r0),"=r"(r1),"=r"(r2),"=r"(r3) : "r"(addr))
#define STS32(addr,v) asm volatile("st.shared.b32 [%0], %1;" :: "r"(addr), "r"(v) : "memory")
#define SWZ(a) ((a) ^ (((a)>>3)&0x70))

__device__ __forceinline__ float2 unpack_bf2(uint32_t v){
    float2 r;
    r.x = __uint_as_float(v << 16);
    r.y = __uint_as_float(v & 0xffff0000u);
    return r;
}

#define CPA16(dst,src) asm volatile("cp.async.cg.shared.global [%0], [%1], 16;" :: "r"((uint32_t)(dst)), "l"(src) : "memory")
#define CPC() asm volatile("cp.async.commit_group;" ::: "memory")
#define CPW0() asm volatile("cp.async.wait_group 0;" ::: "memory")
#define CPW1() asm volatile("cp.async.wait_group 1;" ::: "memory")
#define CPW2() asm volatile("cp.async.wait_group 2;" ::: "memory")

#define LDSM4(r0,r1,r2,r3,addr) \
    asm volatile("ldmatrix.sync.aligned.m8n8.x4.shared.b16 {%0,%1,%2,%3}, [%4];" \
        : "=r"(r0),"=r"(r1),"=r"(r2),"=r"(r3) : "r"(addr))
#define LDSM2(r0,r1,addr) \
    asm volatile("ldmatrix.sync.aligned.m8n8.x2.shared.b16 {%0,%1}, [%2];" \
        : "=r"(r0),"=r"(r1) : "r"(addr))

#define MMA(d,a,b) \
    asm volatile("mma.sync.aligned.m16n8k16.row.col.f32.bf16.bf16.f32 " \
        "{%0,%1,%2,%3},{%4,%5,%6,%7},{%8,%9},{%0,%1,%2,%3};" \
        : "+f"((d)[0]),"+f"((d)[1]),"+f"((d)[2]),"+f"((d)[3]) \
        : "r"((a)[0]),"r"((a)[1]),"r"((a)[2]),"r"((a)[3]),"r"((b)[0]),"r"((b)[1]))

// ---------------- scratch ----------------
__device__ uint32_t g_gib[4096 * 512];          // gi as bf16x2, K padded to 1024
__device__ uint32_t g_ABpack[2 * 16 * CHW];     // W1a^T, W1b^T pre-swizzled (152-row chunks)
__device__ uint32_t g_Bpack[NCHUNK * CHW];      // W1c^T chunks
__device__ uint32_t g_B2pack[3 * CHW];          // W2^T chunks
__device__ uint32_t g_A[4096 * 80];             // (gi@W1a + b1) bf16x2 (full 160 cols)
__device__ uint32_t g_B[4096 * 80];             // (gi@W1b) bf16x2
__device__ uint32_t g_T[216 * 80];              // combined phi tables bf16x2 (d*24+g*3+s)
__device__ float g_scores[132096];
__device__ int   g_starts[2048];

// ============================================================
// warp MMA consumer. NK = compile-time k16 count (full unroll).
// TAIL=true: N40 (2xLDSM4 + LDSM2). TAIL=false: N32.
// ============================================================
template<int MT, bool TAIL, int NK>
__device__ __forceinline__ void mma_chunk40(uint32_t Ab, uint32_t Bb,
                                            int mrow0, int nrow0, int lane,
                                            float (&acc)[MT][5][4])
{
    const int a_row = mrow0 + ((lane>>3)&1)*8 + (lane&7);
    const int a_cb  = (lane>>4)*16;
    const int b_row = nrow0 + ((lane>>4)&1)*8 + (lane&7);
    const int b_cb  = ((lane>>3)&1)*16;
    const int b2_row = nrow0 + 32 + (lane&7);
    const int b2_cb  = ((lane>>3)&1)*16;
    #pragma unroll
    for (int k16 = 0; k16 < NK; k16++) {
        const int kb = k16 * 32;
        uint32_t a[MT][4];
        #pragma unroll
        for (int mt = 0; mt < MT; mt++) {
            uint32_t ad = Ab + SWZ((uint32_t)((a_row + mt*16)*128 + kb + a_cb));
            LDSM4(a[mt][0], a[mt][1], a[mt][2], a[mt][3], ad);
        }
        uint32_t b[5][2];
        #pragma unroll
        for (int g = 0; g < 2; g++) {
            uint32_t bd = Bb + SWZ((uint32_t)((b_row + g*16)*128 + kb + b_cb));
            uint32_t r0, r1, r2, r3;
            LDSM4(r0, r1, r2, r3, bd);
            b[2*g][0] = r0; b[2*g][1] = r1; b[2*g+1][0] = r2; b[2*g+1][1] = r3;
        }
        if constexpr (TAIL) {
            uint32_t bd = Bb + SWZ((uint32_t)(b2_row*128 + kb + b2_cb));
            LDSM2(b[4][0], b[4][1], bd);
        }
        #pragma unroll
        for (int mt = 0; mt < MT; mt++)
            #pragma unroll
            for (int nt = 0; nt < (TAIL ? 5 : 4); nt++)
                MMA(acc[mt][nt], a[mt], b[nt]);
    }
}

// ============================================================
// prep (fused: vectorized gi pack + coalesced weight packs + phi tables + fill + starts)
// weight pack index: r = kp*152 + n  (consecutive threads -> consecutive n)
// ============================================================
__global__ void k_prep(const float* __restrict__ gi, const float* __restrict__ W1,
                       const float* __restrict__ W2,
                       const float* __restrict__ de, const float* __restrict__ ge,
                       const float* __restrict__ se,
                       const int* __restrict__ offs, const int* __restrict__ segs,
                       float* __restrict__ out, int NSPAN, int P, int out_total)
{
    long long idx = (long long)blockIdx.x * 256 + threadIdx.x;
    const long long NG  = (long long)NSPAN * 128;           // 8 floats per thread
    const long long AB  = NG + 2 * 16 * CHW;
    const long long BP  = AB + NCHUNK * CHW;
    const long long B2E = BP + 3 * CHW;
    const long long TE  = B2E + 216 * 80;
    const long long FE  = TE + out_total;
    const long long SE  = FE + P;
    if (idx < NG) {
        int n = (int)(idx >> 7), w4 = (int)(idx & 127);
        int c0 = w4 * 8;
        uint4 outw;
        if (c0 + 8 <= GDIM) {
            float4 f0 = *(const float4*)(gi + (size_t)n * GDIM + c0);
            float4 f1 = *(const float4*)(gi + (size_t)n * GDIM + c0 + 4);
            CVTB2(outw.x, f0.x, f0.y); CVTB2(outw.y, f0.z, f0.w);
            CVTB2(outw.z, f1.x, f1.y); CVTB2(outw.w, f1.z, f1.w);
        } else {
            float f[8];
            #pragma unroll
            for (int e = 0; e < 8; e++)
                f[e] = (c0 + e < GDIM) ? gi[(size_t)n * GDIM + c0 + e] : 0.f;
            CVTB2(outw.x, f[0], f[1]); CVTB2(outw.y, f[2], f[3]);
            CVTB2(outw.z, f[4], f[5]); CVTB2(outw.w, f[6], f[7]);
        }
        ((uint4*)g_gib)[idx] = outw;
    } else if (idx < AB) {
        int t = (int)(idx - NG);
        int sel = t / (16 * CHW); int rem = t - sel * 16 * CHW;
        int c = rem / CHW, r = rem % CHW;
        int kp = r / 152, n = r - kp * 152;     // coalesced over n
        int kg = c * 64 + kp * 2;
        float v0 = 0.f, v1 = 0.f;
        if (n < HD) {
            if (kg     < GDIM) v0 = W1[(size_t)(sel * GDIM + kg)     * HD + n];
            if (kg + 1 < GDIM) v1 = W1[(size_t)(sel * GDIM + kg + 1) * HD + n];
        }
        uint32_t w; CVTB2(w, v0, v1);
        uint32_t off = (uint32_t)(n * 128 + kp * 4);
        g_ABpack[(sel * 16 + c) * CHW + (SWZ(off) >> 2)] = w;
    } else if (idx < BP) {
        int t = (int)(idx - AB);
        int c = t / CHW, r = t % CHW;
        int kp = r / 152, n = r - kp * 152;
        int kg = c * 64 + kp * 2;
        float v0 = 0.f, v1 = 0.f;
        if (n < HD) {
            if (kg     < GDIM) v0 = W1[(size_t)(2000 + kg) * HD + n];
            if (kg + 1 < GDIM) v1 = W1[(size_t)(2001 + kg) * HD + n];
        }
        uint32_t w; CVTB2(w, v0, v1);
        uint32_t off = (uint32_t)(n * 128 + kp * 4);
        g_Bpack[c * CHW + (SWZ(off) >> 2)] = w;
    } else if (idx < B2E) {
        int t = (int)(idx - BP);
        int c = t / CHW, r = t % CHW;
        int kp = r / 152, n = r - kp * 152;
        int kg = c * 64 + kp * 2;
        float v0 = 0.f, v1 = 0.f;
        if (n < HD) {
            if (kg     < HD) v0 = W2[(size_t)kg       * HD + n];
            if (kg + 1 < HD) v1 = W2[(size_t)(kg + 1) * HD + n];
        }
        uint32_t w; CVTB2(w, v0, v1);
        uint32_t off = (uint32_t)(n * 128 + kp * 4);
        g_B2pack[c * CHW + (SWZ(off) >> 2)] = w;
    } else if (idx < TE) {
        int t = (int)(idx - B2E);
        int r = t / 80, cc = (t % 80) * 2;
        int d = r / 24, rem = r % 24;
        int g = rem / 3, s = rem % 3;
        float v0 = 0.f, v1 = 0.f;
        if (cc < HD) {
            for (int k = 0; k < 20; k++) {
                float ed = de[d * 20 + k], eg = ge[g * 20 + k], es = se[s * 20 + k];
                v0 += ed * W1[(size_t)(3000 + k) * HD + cc]
                    + eg * W1[(size_t)(3020 + k) * HD + cc]
                    + es * W1[(size_t)(3040 + k) * HD + cc];
                if (cc + 1 < HD)
                    v1 += ed * W1[(size_t)(3000 + k) * HD + cc + 1]
                        + eg * W1[(size_t)(3020 + k) * HD + cc + 1]
                        + es * W1[(size_t)(3040 + k) * HD + cc + 1];
            }
        }
        uint32_t w; CVTB2(w, v0, v1);
        g_T[r * 80 + (cc >> 1)] = w;
    } else if (idx < FE) {
        long long i = idx - TE;
        out[i] = (i == 0) ? 1.0f : 1000.0f;
    } else if (idx < SE) {
        int p = (int)(idx - FE);
        if (offs[p] == 0) g_starts[segs[p]] = p;
    }
}

// ============================================================
// k_pre: g_A = (gi @ W1a) + b1, g_B = gi @ W1b  (bf16x2 output, full 160 cols)
// grid (NSPAN/64, 2, 2): x = M64 tile, y = sel, z = N-half
// ============================================================
__global__ __launch_bounds__(256) void k_pre(const float* __restrict__ b1)
{
    extern __shared__ char dsm[];
    const int tid = threadIdx.x;
    const int lane = tid & 31;
    const int wid = tid >> 5;
    const int mw = wid & 3, nh = wid >> 2;
    const int n0 = blockIdx.x * 64;
    const int sel = blockIdx.y;
    const int z = blockIdx.z;

    uint32_t rbase = (smem_u32(dsm) + 1023u) & ~1023u;
    const char* Bsrc = (const char*)(g_ABpack + sel * 16 * CHW) + (z ? 10240 : 0);
    const int nB = z ? 576 : 640;

    float acc[1][5][4];
    #pragma unroll
    for (int j = 0; j < 5; j++)
        #pragma unroll
        for (int k = 0; k < 4; k++) acc[0][j][k] = 0.f;

    auto issue = [&](int c) {
        int s = c & 3;
        uint32_t Ab = rbase + (uint32_t)(s * 8192);
        uint32_t Bb = rbase + 32768u + (uint32_t)(s * 10240);
        #pragma unroll
        for (int t = 0; t < 2; t++) {
            int i = tid + t * 256;
            int row = i >> 3, seg = i & 7;
            const char* src = (const char*)g_gib + ((size_t)(n0 + row) * 2048 + c * 128 + seg * 16);
            CPA16(Ab + SWZ((uint32_t)(row * 128 + seg * 16)), src);
        }
        #pragma unroll
        for (int t = 0; t < 3; t++) {
            int j = tid + t * 256;
            if (j < nB) CPA16(Bb + (uint32_t)(j * 16), Bsrc + (size_t)c * CHB + j * 16);
        }
        CPC();
    };

    const bool tail = !(z == 1 && nh == 1);

    issue(0); issue(1); issue(2);
    for (int c = 0; c < 16; c++) {
        if (c <= 13) CPW2(); else if (c == 14) CPW1(); else CPW0();
        __syncthreads();
        if (c + 3 < 16) issue(c + 3);
        int s = c & 3;
        uint32_t Ab = rbase + (uint32_t)(s * 8192);
        uint32_t Bb = rbase + 32768u + (uint32_t)(s * 10240);
        if (c < 15) {
            if (tail) mma_chunk40<1,true ,4>(Ab, Bb, mw * 16, nh * 40, lane, acc);
            else      mma_chunk40<1,false,4>(Ab, Bb, mw * 16, nh * 40, lane, acc);
        } else {
            if (tail) mma_chunk40<1,true ,3>(Ab, Bb, mw * 16, nh * 40, lane, acc);
            else      mma_chunk40<1,false,3>(Ab, Bb, mw * 16, nh * 40, lane, acc);
        }
    }

    uint32_t* dst = sel ? g_B : g_A;
    #pragma unroll
    for (int half = 0; half < 2; half++) {
        int row = n0 + mw * 16 + (lane >> 2) + half * 8;
        #pragma unroll
        for (int nt = 0; nt < 5; nt++) {
            int cc = z * 80 + nh * 40 + nt * 8 + (lane & 3) * 2;
            float x = acc[0][nt][half * 2];
            float y = acc[0][nt][half * 2 + 1];
            if (!sel) {
                if (cc     < HD) x += b1[cc];
                if (cc + 1 < HD) y += b1[cc + 1];
            }
            uint32_t w; CVTB2(w, x, y);
            dst[(size_t)row * 80 + (cc >> 1)] = w;
        }
    }
}

// ============================================================
// fused pair kernel: layer1 HMMA + two-pass epilogue(+tables) + layer2 + score
// ============================================================
__global__ __launch_bounds__(512) void k_fused(
    const float* __restrict__ b2,
    const float* __restrict__ W3, const float* __restrict__ b3,
    const float* __restrict__ ms,
    const int* __restrict__ mi, const int* __restrict__ ai,
    const int* __restrict__ di, const int* __restrict__ gx, const int* __restrict__ si,
    int P)
{
    extern __shared__ char dsm[];
    __shared__ int smi[128], sai[128], sti[128];
    __shared__ __align__(16) float s_b2[HP], s_w3[HP];
    __shared__ float sred[128][4];

    const int tid = threadIdx.x;
    const int lane = tid & 31;
    const int wid = tid >> 5;
    const int mw = wid & 3, nw = wid >> 2;
    const int p0 = blockIdx.x * 128;

    uint32_t rbase = (smem_u32(dsm) + 1023u) & ~1023u;
    const uint32_t Hb  = rbase;                 // 3 x 16KB = 49152
    const uint32_t W2b = rbase + 49152u;        // 3 x 19456 = 58368

    if (tid < 128) {
        int p = p0 + tid; if (p >= P) p = P - 1;
        smi[tid] = mi[p]; sai[tid] = ai[p];
        sti[tid] = di[p] * 24 + gx[p] * 3 + si[p];
    }
    if (tid >= 256 && tid < 256 + HP) {
        int h = tid - 256;
        s_b2[h] = (h < HD) ? b2[h] : 0.f;
        s_w3[h] = (h < HD) ? W3[h] : 0.f;
    }
    __syncthreads();

    float acc[2][5][4];
    #pragma unroll
    for (int i = 0; i < 2; i++)
        #pragma unroll
        for (int j = 0; j < 5; j++)
            #pragma unroll
            for (int k = 0; k < 4; k++) acc[i][j][k] = 0.f;

    const int m = tid >> 2, q = tid & 3;

    uint4 iA[2], jA[2];
    auto loadA = [&](int c) {
        const uint4* Ip = ((const uint4*)g_gib) + ((size_t)smi[m] * 128 + c * 8 + q * 2);
        const uint4* Jp = ((const uint4*)g_gib) + ((size_t)sai[m] * 128 + c * 8 + q * 2);
        iA[0] = Ip[0]; iA[1] = Ip[1];
        jA[0] = Jp[0]; jA[1] = Jp[1];
    };
    auto storeA = [&](int c) {
        uint32_t asb = rbase + (uint32_t)((c & 1) * 16384) + (uint32_t)(m * 128 + q * 32);
        #pragma unroll
        for (int t = 0; t < 2; t++) {
            uint4 r;
            r.x = mul2(iA[t].x, jA[t].x); r.y = mul2(iA[t].y, jA[t].y);
            r.z = mul2(iA[t].z, jA[t].z); r.w = mul2(iA[t].w, jA[t].w);
            STS128(r.x, r.y, r.z, r.w, SWZ(asb + t * 16));
        }
    };
    auto issueB = [&](int c) {
        uint32_t Bb = rbase + 32768u + (uint32_t)((c & 3) * CHB);
        const char* src = (const char*)(g_Bpack + c * CHW);
        #pragma unroll
        for (int t = 0; t < 3; t++) {
            int i = tid + t * 512;
            if (i < 1216) CPA16(Bb + (uint32_t)(i * 16), src + (size_t)i * 16);
        }
        CPC();
    };

    // ---- layer 1 pipeline: B 3 chunks ahead, 1 barrier/chunk ----
    issueB(0); issueB(1); issueB(2);
    loadA(0);
    storeA(0);
    for (int c = 0; c < NCHUNK; c++) {
        if (c + 1 < NCHUNK) loadA(c + 1);
        if (c < NCHUNK - 2) CPW2(); else if (c == NCHUNK - 2) CPW1(); else CPW0();
        __syncthreads();
        if (c + 3 < NCHUNK) issueB(c + 3);
        int s = c & 3;
        uint32_t Ab = rbase + (uint32_t)((c & 1) * 16384);
        uint32_t Bb = rbase + 32768u + (uint32_t)(s * CHB);
        if (c < NCHUNK - 1) {
            if (nw < 3) mma_chunk40<2,true ,4>(Ab, Bb, mw * 32, nw * 40, lane, acc);
            else        mma_chunk40<2,false,4>(Ab, Bb, mw * 32, nw * 40, lane, acc);
        } else {
            if (nw < 3) mma_chunk40<2,true ,3>(Ab, Bb, mw * 32, nw * 40, lane, acc);
            else        mma_chunk40<2,false,3>(Ab, Bb, mw * 32, nw * 40, lane, acc);
        }
        if (c + 1 < NCHUNK) storeA(c + 1);
    }
    __syncthreads();   // all MMA reads done before H/W2 overwrite A/B regions

    // ---- W2^T cp.async ----
    {
        const char* src = (const char*)g_B2pack;
        #pragma unroll
        for (int t = 0; t < 8; t++) {
            int i = tid + t * 512;
            if (i < 3648) CPA16(W2b + (uint32_t)(i * 16), src + (size_t)i * 16);
        }
        CPC();
    }

    // ---- epilogue 1 pass A: raw acc -> bf16 H tile (all cols, zeros in tail) ----
    #pragma unroll
    for (int mt = 0; mt < 2; mt++)
        #pragma unroll
        for (int half = 0; half < 2; half++) {
            int r = mw * 32 + mt * 16 + (lane >> 2) + half * 8;
            #pragma unroll
            for (int nt = 0; nt < 5; nt++) {
                int cc = nw * 40 + nt * 8 + (lane & 3) * 2;
                uint32_t w; CVTB2(w, acc[mt][nt][half * 2], acc[mt][nt][half * 2 + 1]);
                int ch = cc >> 6;
                STS32(Hb + (uint32_t)(ch * 16384) + SWZ((uint32_t)(r * 128 + (cc & 63) * 2)), w);
            }
        }
    __syncthreads();

    // ---- epilogue 1 pass B: vectorized gather + base add + relu (in place) ----
    {
        int r = tid >> 2, qq = tid & 3;
        const uint4* Ar = ((const uint4*)(g_A + (size_t)smi[r] * 80)) + qq * 5;
        const uint4* Br = ((const uint4*)(g_B + (size_t)sai[r] * 80)) + qq * 5;
        const uint4* Tr = ((const uint4*)(g_T + (size_t)sti[r] * 80)) + qq * 5;
        uint4 a4[5], b4[5], t4[5];
        #pragma unroll
        for (int g = 0; g < 5; g++) { a4[g] = Ar[g]; b4[g] = Br[g]; t4[g] = Tr[g]; }
        #pragma unroll
        for (int g = 0; g < 5; g++) {
            int cc0 = qq * 40 + g * 8;
            uint32_t addr = Hb + (uint32_t)((cc0 >> 6) * 16384) +
                            SWZ((uint32_t)(r * 128 + (cc0 & 63) * 2));
            uint32_t h0, h1, h2, h3;
            LDS128(h0, h1, h2, h3, addr);
            uint32_t hw[4] = {h0, h1, h2, h3};
            const uint32_t* ap = (const uint32_t*)&a4[g];
            const uint32_t* bp = (const uint32_t*)&b4[g];
            const uint32_t* tp = (const uint32_t*)&t4[g];
            #pragma unroll
            for (int wv = 0; wv < 4; wv++) {
                float2 hv = unpack_bf2(hw[wv]);
                float2 av = unpack_bf2(ap[wv]);
                float2 bv = unpack_bf2(bp[wv]);
                float2 tv = unpack_bf2(tp[wv]);
                float x = fmaxf(hv.x + av.x + bv.x + tv.x, 0.f);
                float y = fmaxf(hv.y + av.y + bv.y + tv.y, 0.f);
                CVTB2(hw[wv], x, y);
            }
            STS128(hw[0], hw[1], hw[2], hw[3], addr);
        }
    }
    CPW0();
    __syncthreads();

    // ---- layer 2 ----
    #pragma unroll
    for (int i = 0; i < 2; i++)
        #pragma unroll
        for (int j = 0; j < 5; j++)
            #pragma unroll
            for (int k = 0; k < 4; k++) acc[i][j][k] = 0.f;
    if (nw < 3) {
        mma_chunk40<2,true ,4>(Hb,          W2b,           mw * 32, nw * 40, lane, acc);
        mma_chunk40<2,true ,4>(Hb + 16384u, W2b + CHB,     mw * 32, nw * 40, lane, acc);
        mma_chunk40<2,true ,2>(Hb + 32768u, W2b + 2 * CHB, mw * 32, nw * 40, lane, acc);
    } else {
        mma_chunk40<2,false,4>(Hb,          W2b,           mw * 32, nw * 40, lane, acc);
        mma_chunk40<2,false,4>(Hb + 16384u, W2b + CHB,     mw * 32, nw * 40, lane, acc);
        mma_chunk40<2,false,2>(Hb + 32768u, W2b + 2 * CHB, mw * 32, nw * 40, lane, acc);
    }

    // ---- epilogue 2: relu(+b2) . W3 -> reduce -> scores ----
    #pragma unroll
    for (int mt = 0; mt < 2; mt++)
        #pragma unroll
        for (int half = 0; half < 2; half++) {
            float part = 0.f;
            #pragma unroll
            for (int nt = 0; nt < 5; nt++) {
                int cc = nw * 40 + nt * 8 + (lane & 3) * 2;
                float h0 = fmaxf(acc[mt][nt][half * 2]     + s_b2[cc],     0.f);
                float h1 = fmaxf(acc[mt][nt][half * 2 + 1] + s_b2[cc + 1], 0.f);
                part += h0 * s_w3[cc] + h1 * s_w3[cc + 1];
            }
            part += __shfl_xor_sync(0xffffffffu, part, 1);
            part += __shfl_xor_sync(0xffffffffu, part, 2);
            if ((lane & 3) == 0) {
                int r = mw * 32 + mt * 16 + (lane >> 2) + half * 8;
                sred[r][nw] = part;
            }
        }
    __syncthreads();
    if (tid < 128) {
        int p = p0 + tid;
        if (p < P) {
            float s = sred[tid][0] + sred[tid][1] + sred[tid][2] + sred[tid][3]
                    + b3[0] + ms[smi[tid]] + ms[sai[tid]];
            g_scores[p] = s;
        }
    }
}

// ============================================================
// softmax: 4 groups per 512-thread block
// ============================================================
__global__ __launch_bounds__(512) void k_softmax(const int* __restrict__ lengths,
                                                 float* __restrict__ out, int M)
{
    __shared__ float sm[4][4], ss[4][4];
    int gg = threadIdx.x >> 7;
    int tid = threadIdx.x & 127;
    int g = blockIdx.x * 4 + gg;
    bool ok = (g < M);
    int len = ok ? lengths[g] : 0;
    int st  = ok ? g_starts[g] : 0;

    float v = (ok && tid < len) ? g_scores[st + tid] : -3.4e38f;
    float mx = v;
    #pragma unroll
    for (int o = 16; o > 0; o >>= 1) mx = fmaxf(mx, __shfl_xor_sync(0xffffffffu, mx, o));
    if ((tid & 31) == 0) sm[gg][tid >> 5] = mx;
    __syncthreads();
    mx = fmaxf(fmaxf(sm[gg][0], sm[gg][1]), fmaxf(sm[gg][2], sm[gg][3]));
    mx = fmaxf(mx, 0.f);

    float e = (ok && tid < len) ? expf(v - mx) : 0.f;
    float s = e;
    #pragma unroll
    for (int o = 16; o > 0; o >>= 1) s += __shfl_xor_sync(0xffffffffu, s, o);
    if ((tid & 31) == 0) ss[gg][tid >> 5] = s;
    __syncthreads();

    if (ok) {
        float epse = expf(-mx);
        float denom = ss[gg][0] + ss[gg][1] + ss[gg][2] + ss[gg][3] + epse;
        float* row = out + (size_t)(g + 1) * GRIDW;
        if (tid < len) row[tid] = e / denom;
        if (tid == 0)  row[len] = epse / denom;
    }
}

// ============================================================
extern "C" void kernel_launch(void* const* d_in, const int* in_sizes, int n_in,
                              void* d_out, int out_size)
{
    const float* gi   = (const float*)d_in[0];
    const float* ms   = (const float*)d_in[1];
    const float* de   = (const float*)d_in[2];
    const float* ge   = (const float*)d_in[3];
    const float* se   = (const float*)d_in[4];
    const float* W1   = (const float*)d_in[5];
    const float* b1   = (const float*)d_in[6];
    const float* W2   = (const float*)d_in[7];
    const float* b2   = (const float*)d_in[8];
    const float* W3   = (const float*)d_in[9];
    const float* b3   = (const float*)d_in[10];
    const int*   mi   = (const int*)d_in[11];
    const int*   ai   = (const int*)d_in[12];
    const int*   di   = (const int*)d_in[13];
    const int*   gidx = (const int*)d_in[14];
    const int*   si   = (const int*)d_in[15];
    const int*   lens = (const int*)d_in[16];
    const int*   segs = (const int*)d_in[17];
    const int*   offs = (const int*)d_in[18];
    float* out = (float*)d_out;

    const int P = in_sizes[11];
    const int M = in_sizes[16];
    const int NSPAN = in_sizes[0] / GDIM;   // 4096

    const int DS_PRE   = 73728 + 1024;
    const int DS_FUSED = 110592 + 1024;
    static int configured = 0;
    if (!configured) {
        cudaFuncSetAttribute(k_pre,   cudaFuncAttributeMaxDynamicSharedMemorySize, DS_PRE);
        cudaFuncSetAttribute(k_fused, cudaFuncAttributeMaxDynamicSharedMemorySize, DS_FUSED);
        configured = 1;
    }

    long long prep_total = (long long)NSPAN * 128 + (2 * 16 + NCHUNK + 3) * CHW
                         + 216 * 80 + out_size + P;
    k_prep<<<(int)((prep_total + 255) / 256), 256>>>(gi, W1, W2, de, ge, se,
                                                     offs, segs, out,
                                                     NSPAN, P, out_size);

    k_pre<<<dim3(NSPAN / 64, 2, 2), 256, DS_PRE>>>(b1);

    int NT = (P + 127) / 128;
    k_fused<<<NT, 512, DS_FUSED>>>(b2, W3, b3, ms,
                                   mi, ai, di, gidx, si, P);

    k_softmax<<<(M + 3) / 4, 512>>>(lens, out, M);
}

// round 16
// speedup vs baseline: 1.0068x; 1.0068x over previous
#include <cuda_runtime.h>
#include <cuda_bf16.h>
#include <cstdint>

#define HD 150
#define HP 160
#define GDIM 1000
#define GRIDW 129
#define NCHUNK 16
#define CHW 4864          // words per 152-row B chunk
#define CHB 19456         // bytes per 152-row B chunk (1024-aligned)

typedef unsigned long long ull;

// ---------------- helpers ----------------
__device__ __forceinline__ uint32_t smem_u32(const void* p){
    uint32_t a; asm("{ .reg .u64 t; cvta.to.shared.u64 t, %1; cvt.u32.u64 %0, t; }" : "=r"(a) : "l"(p));
    return a;
}
__device__ __forceinline__ uint32_t mul2(uint32_t a, uint32_t b){
    uint32_t r; asm("mul.bf16x2 %0,%1,%2;" : "=r"(r) : "r"(a), "r"(b)); return r;
}
#define CVTB2(res,a,b) asm("cvt.rn.satfinite.bf16x2.f32 %0, %1, %2;" : "=r"(res) : "f"(b), "f"(a))
#define STS128(r0,r1,r2,r3,addr) asm volatile("st.shared.v4.b32 [%0], {%1,%2,%3,%4};" :: "r"(addr), "r"(r0), "r"(r1), "r"(r2), "r"(r3) : "memory")
#define LDS128(r0,r1,r2,r3,addr) asm volatile("ld.shared.v4.b32 {%0,%1,%2,%3}, [%4];" : "=r"(r0),"=r"(r1),"=r"(r2),"=r"(r3) : "r"(addr))
#define STS32(addr,v) asm volatile("st.shared.b32 [%0], %1;" :: "r"(addr), "r"(v) : "memory")
#define SWZ(a) ((a) ^ (((a)>>3)&0x70))

__device__ __forceinline__ float2 unpack_bf2(uint32_t v){
    float2 r;
    r.x = __uint_as_float(v << 16);
    r.y = __uint_as_float(v & 0xffff0000u);
    return r;
}

#define CPA16(dst,src) asm volatile("cp.async.cg.shared.global [%0], [%1], 16;" :: "r"((uint32_t)(dst)), "l"(src) : "memory")
#define CPC() asm volatile("cp.async.commit_group;" ::: "memory")
#define CPW0() asm volatile("cp.async.wait_group 0;" ::: "memory")
#define CPW1() asm volatile("cp.async.wait_group 1;" ::: "memory")
#define CPW2() asm volatile("cp.async.wait_group 2;" ::: "memory")

#define LDSM4(r0,r1,r2,r3,addr) \
    asm volatile("ldmatrix.sync.aligned.m8n8.x4.shared.b16 {%0,%1,%2,%3}, [%4];" \
        : "=r"(r0),"=r"(r1),"=r"(r2),"=r"(r3) : "r"(addr))
#define LDSM2(r0,r1,addr) \
    asm volatile("ldmatrix.sync.aligned.m8n8.x2.shared.b16 {%0,%1}, [%2];" \
        : "=r"(r0),"=r"(r1) : "r"(addr))

#define MMA(d,a,b) \
    asm volatile("mma.sync.aligned.m16n8k16.row.col.f32.bf16.bf16.f32 " \
        "{%0,%1,%2,%3},{%4,%5,%6,%7},{%8,%9},{%0,%1,%2,%3};" \
        : "+f"((d)[0]),"+f"((d)[1]),"+f"((d)[2]),"+f"((d)[3]) \
        : "r"((a)[0]),"r"((a)[1]),"r"((a)[2]),"r"((a)[3]),"r"((b)[0]),"r"((b)[1]))

// ---------------- scratch ----------------
__device__ uint32_t g_gib[4096 * 512];          // gi as bf16x2, K padded to 1024
__device__ uint32_t g_ABpack[2 * 16 * CHW];     // W1a^T, W1b^T pre-swizzled (152-row chunks)
__device__ uint32_t g_Bpack[NCHUNK * CHW];      // W1c^T chunks
__device__ uint32_t g_B2pack[3 * CHW];          // W2^T chunks
__device__ uint32_t g_A[4096 * 80];             // (gi@W1a + b1) bf16x2 (full 160 cols)
__device__ uint32_t g_B[4096 * 80];             // (gi@W1b) bf16x2
__device__ uint32_t g_T[216 * 80];              // combined phi tables bf16x2 (d*24+g*3+s)
__device__ float g_scores[132096];
__device__ int   g_starts[2048];

// ============================================================
// warp MMA consumer. TAIL=true: N40 (2xLDSM4 + LDSM2). TAIL=false: N32.
// (runtime nk16 — R14-proven variant)
// ============================================================
template<int MT, bool TAIL>
__device__ __forceinline__ void mma_chunk40(uint32_t Ab, uint32_t Bb, int nk16,
                                            int mrow0, int nrow0, int lane,
                                            float (&acc)[MT][5][4])
{
    const int a_row = mrow0 + ((lane>>3)&1)*8 + (lane&7);
    const int a_cb  = (lane>>4)*16;
    const int b_row = nrow0 + ((lane>>4)&1)*8 + (lane&7);
    const int b_cb  = ((lane>>3)&1)*16;
    const int b2_row = nrow0 + 32 + (lane&7);
    const int b2_cb  = ((lane>>3)&1)*16;
    #pragma unroll
    for (int k16 = 0; k16 < nk16; k16++) {
        const int kb = k16 * 32;
        uint32_t a[MT][4];
        #pragma unroll
        for (int mt = 0; mt < MT; mt++) {
            uint32_t ad = Ab + SWZ((uint32_t)((a_row + mt*16)*128 + kb + a_cb));
            LDSM4(a[mt][0], a[mt][1], a[mt][2], a[mt][3], ad);
        }
        uint32_t b[5][2];
        #pragma unroll
        for (int g = 0; g < 2; g++) {
            uint32_t bd = Bb + SWZ((uint32_t)((b_row + g*16)*128 + kb + b_cb));
            uint32_t r0, r1, r2, r3;
            LDSM4(r0, r1, r2, r3, bd);
            b[2*g][0] = r0; b[2*g][1] = r1; b[2*g+1][0] = r2; b[2*g+1][1] = r3;
        }
        if constexpr (TAIL) {
            uint32_t bd = Bb + SWZ((uint32_t)(b2_row*128 + kb + b2_cb));
            LDSM2(b[4][0], b[4][1], bd);
        }
        #pragma unroll
        for (int mt = 0; mt < MT; mt++)
            #pragma unroll
            for (int nt = 0; nt < (TAIL ? 5 : 4); nt++)
                MMA(acc[mt][nt], a[mt], b[nt]);
    }
}

// ============================================================
// prep (fused: vectorized gi pack + coalesced weight packs + phi tables + fill + starts)
// weight pack index: r = kp*152 + n  (consecutive threads -> consecutive n)
// ============================================================
__global__ void k_prep(const float* __restrict__ gi, const float* __restrict__ W1,
                       const float* __restrict__ W2,
                       const float* __restrict__ de, const float* __restrict__ ge,
                       const float* __restrict__ se,
                       const int* __restrict__ offs, const int* __restrict__ segs,
                       float* __restrict__ out, int NSPAN, int P, int out_total)
{
    long long idx = (long long)blockIdx.x * 256 + threadIdx.x;
    const long long NG  = (long long)NSPAN * 128;           // 8 floats per thread
    const long long AB  = NG + 2 * 16 * CHW;
    const long long BP  = AB + NCHUNK * CHW;
    const long long B2E = BP + 3 * CHW;
    const long long TE  = B2E + 216 * 80;
    const long long FE  = TE + out_total;
    const long long SE  = FE + P;
    if (idx < NG) {
        int n = (int)(idx >> 7), w4 = (int)(idx & 127);
        int c0 = w4 * 8;
        uint4 outw;
        if (c0 + 8 <= GDIM) {
            float4 f0 = *(const float4*)(gi + (size_t)n * GDIM + c0);
            float4 f1 = *(const float4*)(gi + (size_t)n * GDIM + c0 + 4);
            CVTB2(outw.x, f0.x, f0.y); CVTB2(outw.y, f0.z, f0.w);
            CVTB2(outw.z, f1.x, f1.y); CVTB2(outw.w, f1.z, f1.w);
        } else {
            float f[8];
            #pragma unroll
            for (int e = 0; e < 8; e++)
                f[e] = (c0 + e < GDIM) ? gi[(size_t)n * GDIM + c0 + e] : 0.f;
            CVTB2(outw.x, f[0], f[1]); CVTB2(outw.y, f[2], f[3]);
            CVTB2(outw.z, f[4], f[5]); CVTB2(outw.w, f[6], f[7]);
        }
        ((uint4*)g_gib)[idx] = outw;
    } else if (idx < AB) {
        int t = (int)(idx - NG);
        int sel = t / (16 * CHW); int rem = t - sel * 16 * CHW;
        int c = rem / CHW, r = rem % CHW;
        int kp = r / 152, n = r - kp * 152;     // coalesced over n
        int kg = c * 64 + kp * 2;
        float v0 = 0.f, v1 = 0.f;
        if (n < HD) {
            if (kg     < GDIM) v0 = W1[(size_t)(sel * GDIM + kg)     * HD + n];
            if (kg + 1 < GDIM) v1 = W1[(size_t)(sel * GDIM + kg + 1) * HD + n];
        }
        uint32_t w; CVTB2(w, v0, v1);
        uint32_t off = (uint32_t)(n * 128 + kp * 4);
        g_ABpack[(sel * 16 + c) * CHW + (SWZ(off) >> 2)] = w;
    } else if (idx < BP) {
        int t = (int)(idx - AB);
        int c = t / CHW, r = t % CHW;
        int kp = r / 152, n = r - kp * 152;
        int kg = c * 64 + kp * 2;
        float v0 = 0.f, v1 = 0.f;
        if (n < HD) {
            if (kg     < GDIM) v0 = W1[(size_t)(2000 + kg) * HD + n];
            if (kg + 1 < GDIM) v1 = W1[(size_t)(2001 + kg) * HD + n];
        }
        uint32_t w; CVTB2(w, v0, v1);
        uint32_t off = (uint32_t)(n * 128 + kp * 4);
        g_Bpack[c * CHW + (SWZ(off) >> 2)] = w;
    } else if (idx < B2E) {
        int t = (int)(idx - BP);
        int c = t / CHW, r = t % CHW;
        int kp = r / 152, n = r - kp * 152;
        int kg = c * 64 + kp * 2;
        float v0 = 0.f, v1 = 0.f;
        if (n < HD) {
            if (kg     < HD) v0 = W2[(size_t)kg       * HD + n];
            if (kg + 1 < HD) v1 = W2[(size_t)(kg + 1) * HD + n];
        }
        uint32_t w; CVTB2(w, v0, v1);
        uint32_t off = (uint32_t)(n * 128 + kp * 4);
        g_B2pack[c * CHW + (SWZ(off) >> 2)] = w;
    } else if (idx < TE) {
        int t = (int)(idx - B2E);
        int r = t / 80, cc = (t % 80) * 2;
        int d = r / 24, rem = r % 24;
        int g = rem / 3, s = rem % 3;
        float v0 = 0.f, v1 = 0.f;
        if (cc < HD) {
            for (int k = 0; k < 20; k++) {
                float ed = de[d * 20 + k], eg = ge[g * 20 + k], es = se[s * 20 + k];
                v0 += ed * W1[(size_t)(3000 + k) * HD + cc]
                    + eg * W1[(size_t)(3020 + k) * HD + cc]
                    + es * W1[(size_t)(3040 + k) * HD + cc];
                if (cc + 1 < HD)
                    v1 += ed * W1[(size_t)(3000 + k) * HD + cc + 1]
                        + eg * W1[(size_t)(3020 + k) * HD + cc + 1]
                        + es * W1[(size_t)(3040 + k) * HD + cc + 1];
            }
        }
        uint32_t w; CVTB2(w, v0, v1);
        g_T[r * 80 + (cc >> 1)] = w;
    } else if (idx < FE) {
        long long i = idx - TE;
        out[i] = (i == 0) ? 1.0f : 1000.0f;
    } else if (idx < SE) {
        int p = (int)(idx - FE);
        if (offs[p] == 0) g_starts[segs[p]] = p;
    }
}

// ============================================================
// k_pre: g_A = (gi @ W1a) + b1, g_B = gi @ W1b  (bf16x2 output, full 160 cols)
// grid (NSPAN/64, 2, 2): x = M64 tile, y = sel, z = N-half
// ============================================================
__global__ __launch_bounds__(256) void k_pre(const float* __restrict__ b1)
{
    extern __shared__ char dsm[];
    const int tid = threadIdx.x;
    const int lane = tid & 31;
    const int wid = tid >> 5;
    const int mw = wid & 3, nh = wid >> 2;
    const int n0 = blockIdx.x * 64;
    const int sel = blockIdx.y;
    const int z = blockIdx.z;

    uint32_t rbase = (smem_u32(dsm) + 1023u) & ~1023u;
    const char* Bsrc = (const char*)(g_ABpack + sel * 16 * CHW) + (z ? 10240 : 0);
    const int nB = z ? 576 : 640;

    float acc[1][5][4];
    #pragma unroll
    for (int j = 0; j < 5; j++)
        #pragma unroll
        for (int k = 0; k < 4; k++) acc[0][j][k] = 0.f;

    auto issue = [&](int c) {
        int s = c & 3;
        uint32_t Ab = rbase + (uint32_t)(s * 8192);
        uint32_t Bb = rbase + 32768u + (uint32_t)(s * 10240);
        #pragma unroll
        for (int t = 0; t < 2; t++) {
            int i = tid + t * 256;
            int row = i >> 3, seg = i & 7;
            const char* src = (const char*)g_gib + ((size_t)(n0 + row) * 2048 + c * 128 + seg * 16);
            CPA16(Ab + SWZ((uint32_t)(row * 128 + seg * 16)), src);
        }
        #pragma unroll
        for (int t = 0; t < 3; t++) {
            int j = tid + t * 256;
            if (j < nB) CPA16(Bb + (uint32_t)(j * 16), Bsrc + (size_t)c * CHB + j * 16);
        }
        CPC();
    };

    const bool tail = !(z == 1 && nh == 1);

    issue(0); issue(1); issue(2);
    for (int c = 0; c < 16; c++) {
        if (c <= 13) CPW2(); else if (c == 14) CPW1(); else CPW0();
        __syncthreads();
        if (c + 3 < 16) issue(c + 3);
        int s = c & 3;
        int nk = (c == 15) ? 3 : 4;
        uint32_t Ab = rbase + (uint32_t)(s * 8192);
        uint32_t Bb = rbase + 32768u + (uint32_t)(s * 10240);
        if (tail) mma_chunk40<1,true >(Ab, Bb, nk, mw * 16, nh * 40, lane, acc);
        else      mma_chunk40<1,false>(Ab, Bb, nk, mw * 16, nh * 40, lane, acc);
    }

    uint32_t* dst = sel ? g_B : g_A;
    #pragma unroll
    for (int half = 0; half < 2; half++) {
        int row = n0 + mw * 16 + (lane >> 2) + half * 8;
        #pragma unroll
        for (int nt = 0; nt < 5; nt++) {
            int cc = z * 80 + nh * 40 + nt * 8 + (lane & 3) * 2;
            float x = acc[0][nt][half * 2];
            float y = acc[0][nt][half * 2 + 1];
            if (!sel) {
                if (cc     < HD) x += b1[cc];
                if (cc + 1 < HD) y += b1[cc + 1];
            }
            uint32_t w; CVTB2(w, x, y);
            dst[(size_t)row * 80 + (cc >> 1)] = w;
        }
    }
}

// ============================================================
// fused pair kernel: layer1 HMMA + two-pass epilogue(+tables) + layer2 + score
// (R14-exact structure)
// ============================================================
__global__ __launch_bounds__(512) void k_fused(
    const float* __restrict__ b2,
    const float* __restrict__ W3, const float* __restrict__ b3,
    const float* __restrict__ ms,
    const int* __restrict__ mi, const int* __restrict__ ai,
    const int* __restrict__ di, const int* __restrict__ gx, const int* __restrict__ si,
    int P)
{
    extern __shared__ char dsm[];
    __shared__ int smi[128], sai[128], sti[128];
    __shared__ __align__(16) float s_b2[HP], s_w3[HP];
    __shared__ float sred[128][4];

    const int tid = threadIdx.x;
    const int lane = tid & 31;
    const int wid = tid >> 5;
    const int mw = wid & 3, nw = wid >> 2;
    const int p0 = blockIdx.x * 128;

    uint32_t rbase = (smem_u32(dsm) + 1023u) & ~1023u;
    const uint32_t Hb  = rbase;                 // 3 x 16KB = 49152
    const uint32_t W2b = rbase + 49152u;        // 3 x 19456 = 58368

    if (tid < 128) {
        int p = p0 + tid; if (p >= P) p = P - 1;
        smi[tid] = mi[p]; sai[tid] = ai[p];
        sti[tid] = di[p] * 24 + gx[p] * 3 + si[p];
    }
    if (tid >= 256 && tid < 256 + HP) {
        int h = tid - 256;
        s_b2[h] = (h < HD) ? b2[h] : 0.f;
        s_w3[h] = (h < HD) ? W3[h] : 0.f;
    }
    __syncthreads();

    float acc[2][5][4];
    #pragma unroll
    for (int i = 0; i < 2; i++)
        #pragma unroll
        for (int j = 0; j < 5; j++)
            #pragma unroll
            for (int k = 0; k < 4; k++) acc[i][j][k] = 0.f;

    const int m = tid >> 2, q = tid & 3;

    uint4 iA[2], jA[2];
    auto loadA = [&](int c) {
        const uint4* Ip = ((const uint4*)g_gib) + ((size_t)smi[m] * 128 + c * 8 + q * 2);
        const uint4* Jp = ((const uint4*)g_gib) + ((size_t)sai[m] * 128 + c * 8 + q * 2);
        iA[0] = Ip[0]; iA[1] = Ip[1];
        jA[0] = Jp[0]; jA[1] = Jp[1];
    };
    auto storeA = [&](int c) {
        uint32_t asb = rbase + (uint32_t)((c & 1) * 16384) + (uint32_t)(m * 128 + q * 32);
        #pragma unroll
        for (int t = 0; t < 2; t++) {
            uint4 r;
            r.x = mul2(iA[t].x, jA[t].x); r.y = mul2(iA[t].y, jA[t].y);
            r.z = mul2(iA[t].z, jA[t].z); r.w = mul2(iA[t].w, jA[t].w);
            STS128(r.x, r.y, r.z, r.w, SWZ(asb + t * 16));
        }
    };
    auto issueB = [&](int c) {
        uint32_t Bb = rbase + 32768u + (uint32_t)((c & 3) * CHB);
        const char* src = (const char*)(g_Bpack + c * CHW);
        #pragma unroll
        for (int t = 0; t < 3; t++) {
            int i = tid + t * 512;
            if (i < 1216) CPA16(Bb + (uint32_t)(i * 16), src + (size_t)i * 16);
        }
        CPC();
    };

    // ---- layer 1 pipeline: B 3 chunks ahead, 1 barrier/chunk ----
    issueB(0); issueB(1); issueB(2);
    loadA(0);
    storeA(0);
    for (int c = 0; c < NCHUNK; c++) {
        if (c + 1 < NCHUNK) loadA(c + 1);
        if (c < NCHUNK - 2) CPW2(); else if (c == NCHUNK - 2) CPW1(); else CPW0();
        __syncthreads();
        if (c + 3 < NCHUNK) issueB(c + 3);
        int s = c & 3;
        int nk = (c == NCHUNK - 1) ? 3 : 4;
        uint32_t Ab = rbase + (uint32_t)((c & 1) * 16384);
        uint32_t Bb = rbase + 32768u + (uint32_t)(s * CHB);
        if (nw < 3) mma_chunk40<2,true >(Ab, Bb, nk, mw * 32, nw * 40, lane, acc);
        else        mma_chunk40<2,false>(Ab, Bb, nk, mw * 32, nw * 40, lane, acc);
        if (c + 1 < NCHUNK) storeA(c + 1);
    }
    __syncthreads();   // all MMA reads done before H/W2 overwrite A/B regions

    // ---- W2^T cp.async ----
    {
        const char* src = (const char*)g_B2pack;
        #pragma unroll
        for (int t = 0; t < 8; t++) {
            int i = tid + t * 512;
            if (i < 3648) CPA16(W2b + (uint32_t)(i * 16), src + (size_t)i * 16);
        }
        CPC();
    }

    // ---- epilogue 1 pass A: raw acc -> bf16 H tile (all cols, zeros in tail) ----
    #pragma unroll
    for (int mt = 0; mt < 2; mt++)
        #pragma unroll
        for (int half = 0; half < 2; half++) {
            int r = mw * 32 + mt * 16 + (lane >> 2) + half * 8;
            #pragma unroll
            for (int nt = 0; nt < 5; nt++) {
                int cc = nw * 40 + nt * 8 + (lane & 3) * 2;
                uint32_t w; CVTB2(w, acc[mt][nt][half * 2], acc[mt][nt][half * 2 + 1]);
                int ch = cc >> 6;
                STS32(Hb + (uint32_t)(ch * 16384) + SWZ((uint32_t)(r * 128 + (cc & 63) * 2)), w);
            }
        }
    __syncthreads();

    // ---- epilogue 1 pass B: vectorized gather + base add + relu (in place) ----
    {
        int r = tid >> 2, qq = tid & 3;
        const uint4* Ar = ((const uint4*)(g_A + (size_t)smi[r] * 80)) + qq * 5;
        const uint4* Br = ((const uint4*)(g_B + (size_t)sai[r] * 80)) + qq * 5;
        const uint4* Tr = ((const uint4*)(g_T + (size_t)sti[r] * 80)) + qq * 5;
        uint4 a4[5], b4[5], t4[5];
        #pragma unroll
        for (int g = 0; g < 5; g++) { a4[g] = Ar[g]; b4[g] = Br[g]; t4[g] = Tr[g]; }
        #pragma unroll
        for (int g = 0; g < 5; g++) {
            int cc0 = qq * 40 + g * 8;
            uint32_t addr = Hb + (uint32_t)((cc0 >> 6) * 16384) +
                            SWZ((uint32_t)(r * 128 + (cc0 & 63) * 2));
            uint32_t h0, h1, h2, h3;
            LDS128(h0, h1, h2, h3, addr);
            uint32_t hw[4] = {h0, h1, h2, h3};
            const uint32_t* ap = (const uint32_t*)&a4[g];
            const uint32_t* bp = (const uint32_t*)&b4[g];
            const uint32_t* tp = (const uint32_t*)&t4[g];
            #pragma unroll
            for (int wv = 0; wv < 4; wv++) {
                float2 hv = unpack_bf2(hw[wv]);
                float2 av = unpack_bf2(ap[wv]);
                float2 bv = unpack_bf2(bp[wv]);
                float2 tv = unpack_bf2(tp[wv]);
                float x = fmaxf(hv.x + av.x + bv.x + tv.x, 0.f);
                float y = fmaxf(hv.y + av.y + bv.y + tv.y, 0.f);
                CVTB2(hw[wv], x, y);
            }
            STS128(hw[0], hw[1], hw[2], hw[3], addr);
        }
    }
    CPW0();
    __syncthreads();

    // ---- layer 2 ----
    #pragma unroll
    for (int i = 0; i < 2; i++)
        #pragma unroll
        for (int j = 0; j < 5; j++)
            #pragma unroll
            for (int k = 0; k < 4; k++) acc[i][j][k] = 0.f;
    #pragma unroll
    for (int ch = 0; ch < 3; ch++) {
        int nk = (ch == 2) ? 2 : 4;
        if (nw < 3) mma_chunk40<2,true >(Hb + ch * 16384, W2b + ch * CHB, nk, mw * 32, nw * 40, lane, acc);
        else        mma_chunk40<2,false>(Hb + ch * 16384, W2b + ch * CHB, nk, mw * 32, nw * 40, lane, acc);
    }

    // ---- epilogue 2: relu(+b2) . W3 -> reduce -> scores ----
    #pragma unroll
    for (int mt = 0; mt < 2; mt++)
        #pragma unroll
        for (int half = 0; half < 2; half++) {
            float part = 0.f;
            #pragma unroll
            for (int nt = 0; nt < 5; nt++) {
                int cc = nw * 40 + nt * 8 + (lane & 3) * 2;
                float h0 = fmaxf(acc[mt][nt][half * 2]     + s_b2[cc],     0.f);
                float h1 = fmaxf(acc[mt][nt][half * 2 + 1] + s_b2[cc + 1], 0.f);
                part += h0 * s_w3[cc] + h1 * s_w3[cc + 1];
            }
            part += __shfl_xor_sync(0xffffffffu, part, 1);
            part += __shfl_xor_sync(0xffffffffu, part, 2);
            if ((lane & 3) == 0) {
                int r = mw * 32 + mt * 16 + (lane >> 2) + half * 8;
                sred[r][nw] = part;
            }
        }
    __syncthreads();
    if (tid < 128) {
        int p = p0 + tid;
        if (p < P) {
            float s = sred[tid][0] + sred[tid][1] + sred[tid][2] + sred[tid][3]
                    + b3[0] + ms[smi[tid]] + ms[sai[tid]];
            g_scores[p] = s;
        }
    }
}

// ============================================================
// softmax: 4 groups per 512-thread block
// ============================================================
__global__ __launch_bounds__(512) void k_softmax(const int* __restrict__ lengths,
                                                 float* __restrict__ out, int M)
{
    __shared__ float sm[4][4], ss[4][4];
    int gg = threadIdx.x >> 7;
    int tid = threadIdx.x & 127;
    int g = blockIdx.x * 4 + gg;
    bool ok = (g < M);
    int len = ok ? lengths[g] : 0;
    int st  = ok ? g_starts[g] : 0;

    float v = (ok && tid < len) ? g_scores[st + tid] : -3.4e38f;
    float mx = v;
    #pragma unroll
    for (int o = 16; o > 0; o >>= 1) mx = fmaxf(mx, __shfl_xor_sync(0xffffffffu, mx, o));
    if ((tid & 31) == 0) sm[gg][tid >> 5] = mx;
    __syncthreads();
    mx = fmaxf(fmaxf(sm[gg][0], sm[gg][1]), fmaxf(sm[gg][2], sm[gg][3]));
    mx = fmaxf(mx, 0.f);

    float e = (ok && tid < len) ? expf(v - mx) : 0.f;
    float s = e;
    #pragma unroll
    for (int o = 16; o > 0; o >>= 1) s += __shfl_xor_sync(0xffffffffu, s, o);
    if ((tid & 31) == 0) ss[gg][tid >> 5] = s;
    __syncthreads();

    if (ok) {
        float epse = expf(-mx);
        float denom = ss[gg][0] + ss[gg][1] + ss[gg][2] + ss[gg][3] + epse;
        float* row = out + (size_t)(g + 1) * GRIDW;
        if (tid < len) row[tid] = e / denom;
        if (tid == 0)  row[len] = epse / denom;
    }
}

// ============================================================
extern "C" void kernel_launch(void* const* d_in, const int* in_sizes, int n_in,
                              void* d_out, int out_size)
{
    const float* gi   = (const float*)d_in[0];
    const float* ms   = (const float*)d_in[1];
    const float* de   = (const float*)d_in[2];
    const float* ge   = (const float*)d_in[3];
    const float* se   = (const float*)d_in[4];
    const float* W1   = (const float*)d_in[5];
    const float* b1   = (const float*)d_in[6];
    const float* W2   = (const float*)d_in[7];
    const float* b2   = (const float*)d_in[8];
    const float* W3   = (const float*)d_in[9];
    const float* b3   = (const float*)d_in[10];
    const int*   mi   = (const int*)d_in[11];
    const int*   ai   = (const int*)d_in[12];
    const int*   di   = (const int*)d_in[13];
    const int*   gidx = (const int*)d_in[14];
    const int*   si   = (const int*)d_in[15];
    const int*   lens = (const int*)d_in[16];
    const int*   segs = (const int*)d_in[17];
    const int*   offs = (const int*)d_in[18];
    float* out = (float*)d_out;

    const int P = in_sizes[11];
    const int M = in_sizes[16];
    const int NSPAN = in_sizes[0] / GDIM;   // 4096

    const int DS_PRE   = 73728 + 1024;
    const int DS_FUSED = 110592 + 1024;
    static int configured = 0;
    if (!configured) {
        cudaFuncSetAttribute(k_pre,   cudaFuncAttributeMaxDynamicSharedMemorySize, DS_PRE);
        cudaFuncSetAttribute(k_fused, cudaFuncAttributeMaxDynamicSharedMemorySize, DS_FUSED);
        configured = 1;
    }

    long long prep_total = (long long)NSPAN * 128 + (2 * 16 + NCHUNK + 3) * CHW
                         + 216 * 80 + out_size + P;
    k_prep<<<(int)((prep_total + 255) / 256), 256>>>(gi, W1, W2, de, ge, se,
                                                     offs, segs, out,
                                                     NSPAN, P, out_size);

    k_pre<<<dim3(NSPAN / 64, 2, 2), 256, DS_PRE>>>(b1);

    int NT = (P + 127) / 128;
    k_fused<<<NT, 512, DS_FUSED>>>(b2, W3, b3, ms,
                                   mi, ai, di, gidx, si, P);

    k_softmax<<<(M + 3) / 4, 512>>>(lens, out, M);
}